// round 11
// baseline (speedup 1.0000x reference)
#include <cuda_runtime.h>
#include <cstdint>

#define DIMS   256
#define BATCH  2048
#define NPAIR  32896              // 256*257/2 upper-triangle pairs
#define NROWS  33280              // 260 tiles * 128 rows
#define BM     128
#define BN     256
#define THREADS 256
#define STAGE_BYTES (BM * 128 * 4)               // 64 KB: K=128 half, 4 sub-tiles
#define SMEM_BYTES  (2 * STAGE_BYTES + BN * 4)   // 129 KB

// ---- device scratch (allocation-free) ----
__device__ float    g_c3p[NROWS * DIMS];         // 34 MB packed A, row-major, tf32-rounded
__device__ uint32_t g_pairIdx[NROWS];            // (i<<16)|j per row
// B fragment-major: word = ((ng*16 + kp)*32 + lane)*4 + r
//   ng=b>>3, kp=k>>4, lane=(b&7)*4+(k&3), r=((k>>3)&1)*2+((k&7)>>2)
__device__ float    g_relf[BATCH * DIMS];        // 2 MB, tf32-rounded
__device__ float    g_relT[(DIMS + 1) * BATCH];  // rel^T exact; row 256 = 1.0

static __device__ __forceinline__ float f2tf32f(float f) {
    uint32_t r;
    asm("cvt.rna.tf32.f32 %0, %1;" : "=r"(r) : "f"(f));
    return __uint_as_float(r);
}

#define MMA_TF32(C, A0, A1, A2, A3, B0, B1)                                   \
    asm volatile(                                                             \
        "mma.sync.aligned.m16n8k8.row.col.f32.tf32.tf32.f32 "                 \
        "{%0,%1,%2,%3}, {%4,%5,%6,%7}, {%8,%9}, {%0,%1,%2,%3};"               \
        : "+f"((C)[0]), "+f"((C)[1]), "+f"((C)[2]), "+f"((C)[3])              \
        : "r"(A0), "r"(A1), "r"(A2), "r"(A3), "r"(B0), "r"(B1))

#define LDSM4(R, addr)                                                        \
    asm volatile("ldmatrix.sync.aligned.m8n8.x4.shared.b16 {%0,%1,%2,%3}, [%4];" \
        : "=r"((R)[0]), "=r"((R)[1]), "=r"((R)[2]), "=r"((R)[3])              \
        : "r"(addr))

static __device__ __forceinline__ void cp16(uint32_t dst, const void* gsrc) {
    asm volatile("cp.async.cg.shared.global [%0], [%1], 16;"
                 :: "r"(dst), "l"(gsrc) : "memory");
}
#define CP_COMMIT() asm volatile("cp.async.commit_group;" ::: "memory")
#define CP_WAIT(n)  asm volatile("cp.async.wait_group %0;" :: "n"(n) : "memory")

static __device__ __forceinline__ uint32_t smem_u32(const void* p) {
    uint32_t a;
    asm("{ .reg .u64 t; cvta.to.shared.u64 t, %1; cvt.u32.u64 %0, t; }" : "=r"(a) : "l"(p));
    return a;
}

// ---------------------------------------------------------------------------
__global__ void prep_rel_kernel(const float* __restrict__ x,
                                const float* __restrict__ offsets) {
    int idx = blockIdx.x * blockDim.x + threadIdx.x;   // k*BATCH + b
    int k = idx / BATCH;
    int b = idx % BATCH;
    if (k < DIMS) {
        float r = x[b * DIMS + k] - offsets[k];
        g_relT[idx] = r;
        int ng = b >> 3, kp = k >> 4;
        int lane = (b & 7) * 4 + (k & 3);
        int rr = (((k >> 3) & 1) << 1) | ((k & 7) >> 2);
        ((uint32_t*)g_relf)[((ng * 16 + kp) * 32 + lane) * 4 + rr] =
            __float_as_uint(f2tf32f(r));
    } else {
        g_relT[idx] = 1.0f;
    }
}

__global__ void init_out_kernel(const float* __restrict__ c0p,
                                float* __restrict__ out) {
    int b = blockIdx.x * blockDim.x + threadIdx.x;
    if (b < BATCH) out[b] = c0p[0];
}

// ---------------------------------------------------------------------------
// Pack (coalesced): row-major symmetrized A + pair index table.
// ---------------------------------------------------------------------------
__global__ void pack_kernel(const float* __restrict__ c3,
                            const float* __restrict__ c2,
                            const float* __restrict__ c1) {
    int j = blockIdx.x, i = blockIdx.y, t = threadIdx.x;
    int p;
    float4 v;
    uint32_t pidx;
    if (i < 256) {
        if (j < i) return;
        p = i * 256 - (i * (i - 1)) / 2 + (j - i);
        v = *(const float4*)(c3 + ((size_t)(i * 256 + j)) * DIMS + t * 4);
        if (i != j) {
            float4 w = *(const float4*)(c3 + ((size_t)(j * 256 + i)) * DIMS + t * 4);
            v.x += w.x; v.y += w.y; v.z += w.z; v.w += w.w;
        }
        pidx = ((uint32_t)i << 16) | (uint32_t)j;
    } else if (i == 256) {
        p = NPAIR + j;
        v = *(const float4*)(c2 + (size_t)j * DIMS + t * 4);
        pidx = (256u << 16) | (uint32_t)j;
    } else {
        if (j == 0) {
            p = NPAIR + 256;
            v = *(const float4*)(c1 + t * 4);
        } else if (j < 128) {
            p = NPAIR + 256 + j;
            v = make_float4(0.f, 0.f, 0.f, 0.f);
        } else return;
        pidx = (256u << 16) | 256u;
    }
    v.x = f2tf32f(v.x); v.y = f2tf32f(v.y); v.z = f2tf32f(v.z); v.w = f2tf32f(v.w);
    *(float4*)(g_c3p + (size_t)p * DIMS + t * 4) = v;
    if (t == 0) g_pairIdx[p] = pidx;
}

// ---------------------------------------------------------------------------
// Main: 256 threads, 8 warps = 2M x 4N (64x64 warp tiles, acc 128 regs).
// A: cp.async, 2 stages of K=128 (4 sub-tiles each) -> only 2 barriers total.
// B: direct GMEM fragment loads, double-buffered one k16 ahead.
// ---------------------------------------------------------------------------
__global__ void __launch_bounds__(THREADS) taylor_mma_kernel(
    float* __restrict__ out) {

    extern __shared__ char smem[];
    const uint32_t sb = smem_u32(smem);
    float* sred = (float*)(smem + 2 * STAGE_BYTES);

    const int tid  = threadIdx.x;
    const int lane = tid & 31, wid = tid >> 5;
    const int warpM = wid & 1, warpN = wid >> 1;   // 2 x 4 warps
    const int g = lane >> 2, tig = lane & 3;
    const int p0 = blockIdx.x * BM;
    const int b0 = blockIdx.y * BN;

    sred[tid] = 0.f;                               // BN == 256 == blockDim

    // ---- A cp.async coords (16KB sub-tile, 256 thr => 4 cp16/thread) ----
    const float* Ag = g_c3p + (size_t)p0 * DIMS;
    uint32_t cpdst[4];
    const float* cpsrc[4];
#pragma unroll
    for (int it = 0; it < 4; it++) {
        int idx = tid + it * THREADS;
        int row = idx >> 3, seg = idx & 7;
        cpdst[it] = row * 128 + ((seg ^ (row & 7)) << 4);
        cpsrc[it] = Ag + (size_t)row * DIMS + seg * 4;
    }
    auto cp_stage = [&](int stage) {
        const uint32_t s = sb + stage * STAGE_BYTES;
#pragma unroll
        for (int q = 0; q < 4; q++) {
            const int k0 = stage * 128 + q * 32;
#pragma unroll
            for (int it = 0; it < 4; it++)
                cp16(s + q * 16384 + cpdst[it], cpsrc[it] + k0);
        }
    };

    // ---- B fragment pointer; 8 n-slots per warp ----
    const uint4* bptr = (const uint4*)g_relf
                      + ((size_t)(b0 >> 3) + warpN * 8) * 512 + lane;

    // ---- LDSM addressing (within a 16KB sub-tile) ----
    int aoff[4], axor[4];
#pragma unroll
    for (int msl = 0; msl < 4; msl++) {
        int rowA = warpM * 64 + msl * 16 + ((lane >> 3) & 1) * 8 + (lane & 7);
        aoff[msl] = rowA * 128;
        axor[msl] = rowA & 7;
    }
    const int kcA = (lane >> 4) & 1;

    float acc[4][8][4];
#pragma unroll
    for (int m = 0; m < 4; m++)
#pragma unroll
        for (int n = 0; n < 8; n++)
#pragma unroll
            for (int r = 0; r < 4; r++) acc[m][n][r] = 0.f;

    uint4 Bb0[8], Bb1[8];

    // prologue: both K halves in flight
    cp_stage(0); CP_COMMIT();
    cp_stage(1); CP_COMMIT();

#define LDB(BB, kp)                                                           \
    do {                                                                      \
        _Pragma("unroll")                                                     \
        for (int nsl = 0; nsl < 8; nsl++)                                     \
            (BB)[nsl] = __ldg(bptr + nsl * 512 + (kp) * 32);                  \
    } while (0)

#define COMPUTE_KP(As, KSBASE, BB)                                            \
    do {                                                                      \
        _Pragma("unroll")                                                     \
        for (int ks2 = 0; ks2 < 2; ++ks2) {                                   \
            const int ks = (KSBASE) + ks2;                                    \
            uint32_t a[4][4];                                                 \
            _Pragma("unroll")                                                 \
            for (int msl = 0; msl < 4; ++msl)                                 \
                LDSM4(a[msl], (As) + aoff[msl] +                              \
                      ((((ks << 1) | kcA) ^ axor[msl]) << 4));                \
            _Pragma("unroll")                                                 \
            for (int nsl = 0; nsl < 8; ++nsl) {                               \
                uint32_t b0v = ks2 ? (BB)[nsl].z : (BB)[nsl].x;               \
                uint32_t b1v = ks2 ? (BB)[nsl].w : (BB)[nsl].y;               \
                _Pragma("unroll")                                             \
                for (int msl = 0; msl < 4; ++msl)                             \
                    MMA_TF32(acc[msl][nsl], a[msl][0], a[msl][1],             \
                             a[msl][2], a[msl][3], b0v, b1v);                 \
            }                                                                 \
        }                                                                     \
    } while (0)

    LDB(Bb0, 0);
    CP_WAIT(1);
    __syncthreads();                       // barrier #1: stage 0 resident

#pragma unroll
    for (int stage = 0; stage < 2; ++stage) {
        const uint32_t S = sb + stage * STAGE_BYTES;
#pragma unroll
        for (int q = 0; q < 4; ++q) {
            const uint32_t As = S + q * 16384;
            const int kp = stage * 8 + q * 2;
            LDB(Bb1, kp + 1);
            COMPUTE_KP(As, 0, Bb0);
            if (kp + 2 < 16) LDB(Bb0, kp + 2);
            COMPUTE_KP(As, 2, Bb1);
        }
        if (stage == 0) {
            CP_WAIT(0);
            __syncthreads();               // barrier #2: stage 1 resident
        }
    }

    // ---- epilogue: sred[col] += sum_m D[m,col] * r_i(m)[b] * r_j(m)[b] ----
    const float* wi[4][2];
    const float* wj[4][2];
#pragma unroll
    for (int msl = 0; msl < 4; ++msl)
#pragma unroll
        for (int h = 0; h < 2; ++h) {
            int rloc = warpM * 64 + msl * 16 + h * 8 + g;
            uint32_t pij = g_pairIdx[p0 + rloc];
            wi[msl][h] = g_relT + (size_t)(pij >> 16) * BATCH + b0;
            wj[msl][h] = g_relT + (size_t)(pij & 0xFFFF) * BATCH + b0;
        }

#pragma unroll
    for (int nsl = 0; nsl < 8; ++nsl) {
        const int coln = warpN * 64 + nsl * 8 + tig * 2;
        float s0 = 0.f, s1 = 0.f;
#pragma unroll
        for (int msl = 0; msl < 4; ++msl) {
#pragma unroll
            for (int h = 0; h < 2; ++h) {
                float2 a = *(const float2*)(wi[msl][h] + coln);
                float2 b = *(const float2*)(wj[msl][h] + coln);
                s0 += acc[msl][nsl][2 * h]     * a.x * b.x;
                s1 += acc[msl][nsl][2 * h + 1] * a.y * b.y;
            }
        }
#pragma unroll
        for (int o = 4; o <= 16; o <<= 1) {
            s0 += __shfl_xor_sync(0xFFFFFFFFu, s0, o);
            s1 += __shfl_xor_sync(0xFFFFFFFFu, s1, o);
        }
        if (g == 0) {
            atomicAdd(&sred[coln],     s0);
            atomicAdd(&sred[coln + 1], s1);
        }
    }
    __syncthreads();

    atomicAdd(out + b0 + tid, sred[tid]);
}

// ---------------------------------------------------------------------------
extern "C" void kernel_launch(void* const* d_in, const int* in_sizes, int n_in,
                              void* d_out, int out_size) {
    const float* x       = (const float*)d_in[0];
    const float* offsets = (const float*)d_in[1];
    const float* coeff0  = (const float*)d_in[2];
    const float* coeff1  = (const float*)d_in[3];
    const float* coeff2  = (const float*)d_in[4];
    const float* coeff3  = (const float*)d_in[5];
    float* out = (float*)d_out;

    cudaFuncSetAttribute(taylor_mma_kernel,
                         cudaFuncAttributeMaxDynamicSharedMemorySize, SMEM_BYTES);

    prep_rel_kernel<<<((DIMS + 1) * BATCH) / 256, 256>>>(x, offsets);
    init_out_kernel<<<BATCH / 256, 256>>>(coeff0, out);

    dim3 pgrid(256, 258);
    pack_kernel<<<pgrid, 64>>>(coeff3, coeff2, coeff1);

    dim3 grid(NROWS / BM, BATCH / BN);   // (260, 8)
    taylor_mma_kernel<<<grid, THREADS, SMEM_BYTES>>>(out);
}